// round 14
// baseline (speedup 1.0000x reference)
#include <cuda_runtime.h>
#include <math.h>

#define BB 64
#define SS 512
#define HH 1024
#define G4 4096
#define KSLICES 8
#define GRID 148

// ---------------- scratch (static device globals; no runtime allocation) ----
__device__ float g_pre[(size_t)BB * SS * G4];          // 512 MB
__device__ float g_h0seq[(size_t)BB * SS * HH];        // 128 MB
__device__ float g_partial[(size_t)KSLICES * BB * G4]; // 8 MB
__device__ float g_h0[BB * HH];
__device__ float g_c0[BB * HH];
__device__ float g_h1[BB * HH];
__device__ float g_c1[BB * HH];
__device__ unsigned g_bar[2];

// ---------------- per-launch state init (graph replays must be deterministic)
__global__ void init_state_kernel() {
    int i = blockIdx.x * 256 + threadIdx.x;
    g_h0[i] = 0.f; g_c0[i] = 0.f; g_h1[i] = 0.f; g_c1[i] = 0.f;
    if (i < 2) g_bar[i] = 0u;
}

// ---------------- software grid barrier (all GRID blocks co-resident) -------
__device__ __forceinline__ void gridbar(unsigned* cnt, unsigned target) {
    __syncthreads();
    if (threadIdx.x == 0) {
        __threadfence();                       // release: publish our writes
        atomicAdd(cnt, 1u);
        while (*(volatile unsigned*)cnt < target) { }
    }
    __syncthreads();
}

// ---------------- big input-projection GEMM ---------------------------------
// g_pre[M,4096] = A[M,1024] * W[4096,1024]^T + bi + bh
__global__ __launch_bounds__(256) void gemm_bias_kernel(
    const float* __restrict__ A_ext, int use_internal_A,
    const float* __restrict__ W,
    const float* __restrict__ bi, const float* __restrict__ bh)
{
    const float* __restrict__ A = use_internal_A ? g_h0seq : A_ext;
    const int K = 1024;
    __shared__ float As[16][132];
    __shared__ float Ws[16][132];

    int tx = threadIdx.x;          // 0..15 (n direction)
    int ty = threadIdx.y;          // 0..15 (m direction)
    int tid = ty * 16 + tx;
    int m0 = blockIdx.y * 128;
    int n0 = blockIdx.x * 128;

    float acc[8][8];
#pragma unroll
    for (int i = 0; i < 8; ++i)
#pragma unroll
        for (int j = 0; j < 8; ++j) acc[i][j] = 0.f;

    for (int kt = 0; kt < K; kt += 16) {
#pragma unroll
        for (int q = 0; q < 2; ++q) {
            int idx = tid + 256 * q;
            int row = idx >> 2;
            int c4  = (idx & 3) << 2;
            float4 va = *(const float4*)(A + (size_t)(m0 + row) * K + kt + c4);
            As[c4 + 0][row] = va.x; As[c4 + 1][row] = va.y;
            As[c4 + 2][row] = va.z; As[c4 + 3][row] = va.w;
            float4 vw = *(const float4*)(W + (size_t)(n0 + row) * K + kt + c4);
            Ws[c4 + 0][row] = vw.x; Ws[c4 + 1][row] = vw.y;
            Ws[c4 + 2][row] = vw.z; Ws[c4 + 3][row] = vw.w;
        }
        __syncthreads();
#pragma unroll
        for (int kk = 0; kk < 16; ++kk) {
            float4 a0 = *(const float4*)&As[kk][ty * 8];
            float4 a1 = *(const float4*)&As[kk][ty * 8 + 4];
            float4 b0 = *(const float4*)&Ws[kk][tx * 8];
            float4 b1 = *(const float4*)&Ws[kk][tx * 8 + 4];
            float a[8] = {a0.x, a0.y, a0.z, a0.w, a1.x, a1.y, a1.z, a1.w};
            float b[8] = {b0.x, b0.y, b0.z, b0.w, b1.x, b1.y, b1.z, b1.w};
#pragma unroll
            for (int i = 0; i < 8; ++i)
#pragma unroll
                for (int j = 0; j < 8; ++j)
                    acc[i][j] = fmaf(a[i], b[j], acc[i][j]);
        }
        __syncthreads();
    }

    int n = n0 + tx * 8;
    float bs[8];
#pragma unroll
    for (int j = 0; j < 8; ++j) bs[j] = bi[n + j] + bh[n + j];
#pragma unroll
    for (int i = 0; i < 8; ++i) {
        float* o = g_pre + (size_t)(m0 + ty * 8 + i) * G4 + n;
        *(float4*)o       = make_float4(acc[i][0] + bs[0], acc[i][1] + bs[1],
                                        acc[i][2] + bs[2], acc[i][3] + bs[3]);
        *(float4*)(o + 4) = make_float4(acc[i][4] + bs[4], acc[i][5] + bs[5],
                                        acc[i][6] + bs[6], acc[i][7] + bs[7]);
    }
}

// ---------------- persistent recurrent kernel (one launch per layer) --------
// Per step: 256 GEMM items (32 j-tiles x 8 K-slices), item tile = 64 batch x
// (4 gates x 32 j cols), K chunk 128. Then barrier, pointwise, barrier.
__global__ __launch_bounds__(256) void lstm_layer_kernel(
    const float* __restrict__ Wh, int layer, float* __restrict__ seq_ext)
{
    float* __restrict__ hptr = layer ? g_h1 : g_h0;
    float* __restrict__ cptr = layer ? g_c1 : g_c0;
    float* __restrict__ seq  = layer ? seq_ext : g_h0seq;
    unsigned* bar = &g_bar[layer];

    __shared__ float hs[32][68];
    __shared__ float ws[32][132];

    int tid = threadIdx.x;
    int tx = tid & 31;       // col group: local cols tx*4 .. tx*4+3
    int ty = tid >> 5;       // row group: rows ty*8 .. ty*8+7

    for (int t = 0; t < SS; ++t) {
        // ---- phase 1: split-K step GEMM into g_partial ----
        for (int item = blockIdx.x; item < 32 * KSLICES; item += GRID) {
            int jt = item & 31;
            int ks = item >> 5;
            int j0 = jt * 32;
            int k0 = ks * 128;

            float acc[8][4];
#pragma unroll
            for (int i = 0; i < 8; ++i)
#pragma unroll
                for (int j = 0; j < 4; ++j) acc[i][j] = 0.f;

            for (int ko = 0; ko < 128; ko += 32) {
                int kb = k0 + ko;
                // load h tile: 64 rows x 32 k  (h is cross-block data -> .cg)
#pragma unroll
                for (int q = 0; q < 2; ++q) {
                    int idx = tid + 256 * q;
                    int row = idx >> 3;
                    int c4  = (idx & 7) << 2;
                    float4 v = __ldcg((const float4*)(hptr + (size_t)row * HH + kb + c4));
                    hs[c4 + 0][row] = v.x; hs[c4 + 1][row] = v.y;
                    hs[c4 + 2][row] = v.z; hs[c4 + 3][row] = v.w;
                }
                // load Wh tile: 128 gate-cols x 32 k (read-only weights)
#pragma unroll
                for (int q = 0; q < 4; ++q) {
                    int idx = tid + 256 * q;
                    int c   = idx >> 3;                 // 0..127 local gate col
                    int c4  = (idx & 7) << 2;
                    int grow = ((c >> 5) << 10) + j0 + (c & 31);
                    float4 v = *(const float4*)(Wh + (size_t)grow * HH + kb + c4);
                    ws[c4 + 0][c] = v.x; ws[c4 + 1][c] = v.y;
                    ws[c4 + 2][c] = v.z; ws[c4 + 3][c] = v.w;
                }
                __syncthreads();
#pragma unroll
                for (int kk = 0; kk < 32; ++kk) {
                    float4 a0 = *(const float4*)&hs[kk][ty * 8];
                    float4 a1 = *(const float4*)&hs[kk][ty * 8 + 4];
                    float4 b0 = *(const float4*)&ws[kk][tx * 4];
                    float a[8] = {a0.x, a0.y, a0.z, a0.w, a1.x, a1.y, a1.z, a1.w};
                    float b[4] = {b0.x, b0.y, b0.z, b0.w};
#pragma unroll
                    for (int i = 0; i < 8; ++i)
#pragma unroll
                        for (int j = 0; j < 4; ++j)
                            acc[i][j] = fmaf(a[i], b[j], acc[i][j]);
                }
                __syncthreads();
            }

            int cb = tx * 4;
            int ncol = ((cb >> 5) << 10) + j0 + (cb & 31);
            float* o = g_partial + (size_t)ks * BB * G4 + ncol;
#pragma unroll
            for (int i = 0; i < 8; ++i)
                *(float4*)(o + (size_t)(ty * 8 + i) * G4) =
                    make_float4(acc[i][0], acc[i][1], acc[i][2], acc[i][3]);
        }

        gridbar(bar, (2u * t + 1u) * GRID);

        // ---- phase 2: pointwise gate update ----
        for (int id = blockIdx.x * 256 + tid; id < BB * HH; id += GRID * 256) {
            int b = id >> 10;
            int j = id & (HH - 1);

            const float* pr = g_pre + (size_t)(b * SS + t) * G4 + j;
            float gi = pr[0], gf = pr[HH], gg = pr[2 * HH], go = pr[3 * HH];
#pragma unroll
            for (int s = 0; s < KSLICES; ++s) {
                const float* pp = g_partial + (size_t)(s * BB + b) * G4 + j;
                gi += __ldcg(pp);
                gf += __ldcg(pp + HH);
                gg += __ldcg(pp + 2 * HH);
                go += __ldcg(pp + 3 * HH);
            }

            float iv = 1.f / (1.f + expf(-gi));
            float fv = 1.f / (1.f + expf(-gf));
            float gv = tanhf(gg);
            float ov = 1.f / (1.f + expf(-go));

            float cn = fv * cptr[id] + iv * gv;
            float hn = ov * tanhf(cn);

            cptr[id] = cn;
            hptr[id] = hn;
            seq[(size_t)(b * SS + t) * HH + j] = hn;
        }

        gridbar(bar, (2u * t + 2u) * GRID);
    }
}

// ---------------- final h_n / c_n stacks -------------------------------------
__global__ void finalize_kernel(float* __restrict__ out_h, float* __restrict__ out_c)
{
    int i = blockIdx.x * 256 + threadIdx.x;   // 0..65535
    out_h[i]           = g_h0[i];
    out_h[BB * HH + i] = g_h1[i];
    out_c[i]           = g_c0[i];
    out_c[BB * HH + i] = g_c1[i];
}

// ---------------- launch ------------------------------------------------------
extern "C" void kernel_launch(void* const* d_in, const int* in_sizes, int n_in,
                              void* d_out, int out_size)
{
    const float* x   = (const float*)d_in[0];
    const float* Wi0 = (const float*)d_in[1];
    const float* Wh0 = (const float*)d_in[2];
    const float* bi0 = (const float*)d_in[3];
    const float* bh0 = (const float*)d_in[4];
    const float* Wi1 = (const float*)d_in[5];
    const float* Wh1 = (const float*)d_in[6];
    const float* bi1 = (const float*)d_in[7];
    const float* bh1 = (const float*)d_in[8];

    float* out   = (float*)d_out;                       // [64,512,1024]
    float* out_h = out + (size_t)BB * SS * HH;          // [2,64,1024]
    float* out_c = out_h + (size_t)2 * BB * HH;         // [2,64,1024]

    init_state_kernel<<<BB * HH / 256, 256>>>();

    dim3 gThreads(16, 16);
    dim3 gGrid(G4 / 128, (BB * SS) / 128);              // (32, 256)

    // layer 0
    gemm_bias_kernel<<<gGrid, gThreads>>>(x, 0, Wi0, bi0, bh0);
    lstm_layer_kernel<<<GRID, 256>>>(Wh0, 0, out);

    // layer 1
    gemm_bias_kernel<<<gGrid, gThreads>>>(nullptr, 1, Wi1, bi1, bh1);
    lstm_layer_kernel<<<GRID, 256>>>(Wh1, 1, out);

    finalize_kernel<<<BB * HH / 256, 256>>>(out_h, out_c);
}

// round 16
// speedup vs baseline: 1.3561x; 1.3561x over previous
#include <cuda_runtime.h>
#include <cuda_bf16.h>
#include <math.h>

#define BB 64
#define SS 512
#define HH 1024
#define G4 4096
#define KK 1024
#define KAUG 3072
#define KSL 4          // K-slices in recurrent split-K (768 each)
#define GRID 148
#define MTOT (BB * SS) // 32768

typedef __nv_bfloat16 bf16;

// ---------------- scratch (static device globals; no runtime allocation) ----
__device__ float g_pre[(size_t)MTOT * G4];              // 512 MB fp32
__device__ bf16  g_xaug[(size_t)MTOT * KAUG];           // 201 MB: layer input, aug [hi|lo|hi]
__device__ bf16  g_wi0aug[(size_t)G4 * KAUG];           // 25 MB each
__device__ bf16  g_wh0aug[(size_t)G4 * KAUG];
__device__ bf16  g_wi1aug[(size_t)G4 * KAUG];
__device__ bf16  g_wh1aug[(size_t)G4 * KAUG];
__device__ bf16  g_haug[BB * KAUG];                     // current h, aug
__device__ float g_partial[(size_t)KSL * BB * G4];      // 4 MB split-K partials
__device__ float g_h0[BB * HH];
__device__ float g_c0[BB * HH];
__device__ float g_h1[BB * HH];
__device__ float g_c1[BB * HH];
__device__ unsigned g_bar[2];

// ---------------- PTX helpers -----------------------------------------------
__device__ __forceinline__ void mma_bf16(float* c, const unsigned* a, const unsigned* b) {
    asm volatile(
        "mma.sync.aligned.m16n8k16.row.col.f32.bf16.bf16.f32 "
        "{%0,%1,%2,%3},{%4,%5,%6,%7},{%8,%9},{%0,%1,%2,%3};"
        : "+f"(c[0]), "+f"(c[1]), "+f"(c[2]), "+f"(c[3])
        : "r"(a[0]), "r"(a[1]), "r"(a[2]), "r"(a[3]), "r"(b[0]), "r"(b[1]));
}
__device__ __forceinline__ void ldsm_x4(unsigned* r, unsigned addr) {
    asm volatile("ldmatrix.sync.aligned.m8n8.x4.shared.b16 {%0,%1,%2,%3},[%4];"
                 : "=r"(r[0]), "=r"(r[1]), "=r"(r[2]), "=r"(r[3]) : "r"(addr));
}
__device__ __forceinline__ void ldsm_x2(unsigned* r, unsigned addr) {
    asm volatile("ldmatrix.sync.aligned.m8n8.x2.shared.b16 {%0,%1},[%2];"
                 : "=r"(r[0]), "=r"(r[1]) : "r"(addr));
}

// ---------------- init --------------------------------------------------------
__global__ void init_state_kernel() {
    int i = blockIdx.x * 256 + threadIdx.x;          // grid 384*256 = 98304
    if (i < BB * HH) { g_h0[i] = 0.f; g_c0[i] = 0.f; g_h1[i] = 0.f; g_c1[i] = 0.f; }
    if (i < 2) g_bar[i] = 0u;
    if (i < BB * KAUG / 2) ((unsigned*)g_haug)[i] = 0u;
}

// ---------------- fp32 -> bf16 split conversions ------------------------------
// weights: aug layout [wh | wh | wl]
__global__ void convert_w_kernel(const float* __restrict__ W, bf16* __restrict__ Waug) {
    int idx = blockIdx.x * 256 + threadIdx.x;        // over 4096*1024
    int g = idx >> 10, k = idx & (KK - 1);
    float v = W[idx];
    bf16 hi = __float2bfloat16(v);
    bf16 lo = __float2bfloat16(v - __bfloat162float(hi));
    bf16* row = Waug + (size_t)g * KAUG;
    row[k] = hi; row[k + KK] = hi; row[k + 2 * KK] = lo;
}
// activations: aug layout [hi | lo | hi]
__global__ void convert_x_kernel(const float* __restrict__ X) {
    int idx = blockIdx.x * 256 + threadIdx.x;        // over 32768*1024
    int m = idx >> 10, k = idx & (KK - 1);
    float v = X[idx];
    bf16 hi = __float2bfloat16(v);
    bf16 lo = __float2bfloat16(v - __bfloat162float(hi));
    bf16* row = g_xaug + (size_t)m * KAUG;
    row[k] = hi; row[k + KK] = lo; row[k + 2 * KK] = hi;
}

// ---------------- input-projection GEMM (bf16 tensor-core) --------------------
// g_pre[M,4096] = Aaug[M,3072] * Waug[4096,3072]^T + bi + bh
// Block 128x128, k-chunk 32, 8 warps (2x4), warp tile 64x32.
__global__ __launch_bounds__(256) void gemm_bias_bf16(
    const bf16* __restrict__ A, const bf16* __restrict__ W,
    const float* __restrict__ bi, const float* __restrict__ bh)
{
    __shared__ bf16 As[128 * 40];
    __shared__ bf16 Bs[128 * 40];

    int tid = threadIdx.x;
    int lane = tid & 31, wid = tid >> 5;
    int wm = wid >> 2, wn = wid & 3;
    int m0 = blockIdx.y * 128, n0 = blockIdx.x * 128;

    // global-load mapping: 2 x 16B segs for A, 2 for B per thread
    int r0 = tid >> 2, s0 = tid & 3;
    int r1 = r0 + 64;
    const uint4* Ag0 = (const uint4*)(A + (size_t)(m0 + r0) * KAUG + s0 * 8);
    const uint4* Ag1 = (const uint4*)(A + (size_t)(m0 + r1) * KAUG + s0 * 8);
    const uint4* Bg0 = (const uint4*)(W + (size_t)(n0 + r0) * KAUG + s0 * 8);
    const uint4* Bg1 = (const uint4*)(W + (size_t)(n0 + r1) * KAUG + s0 * 8);

    unsigned sA = (unsigned)__cvta_generic_to_shared(As);
    unsigned sB = (unsigned)__cvta_generic_to_shared(Bs);
    unsigned stoA0 = sA + r0 * 80 + s0 * 16;
    unsigned stoA1 = sA + r1 * 80 + s0 * 16;
    unsigned stoB0 = sB + r0 * 80 + s0 * 16;
    unsigned stoB1 = sB + r1 * 80 + s0 * 16;

    // ldmatrix lane addresses (constant over k-iters)
    unsigned aAddr[4][2], bAddr[4][2];
#pragma unroll
    for (int mt = 0; mt < 4; ++mt)
#pragma unroll
        for (int ks = 0; ks < 2; ++ks)
            aAddr[mt][ks] = sA + (wm * 64 + mt * 16 + (lane & 15)) * 80 + ks * 32 + ((lane >> 4) & 1) * 16;
#pragma unroll
    for (int nt = 0; nt < 4; ++nt)
#pragma unroll
        for (int ks = 0; ks < 2; ++ks)
            bAddr[nt][ks] = sB + (wn * 32 + nt * 8 + (lane & 7)) * 80 + ks * 32 + ((lane >> 3) & 1) * 16;

    float acc[4][4][4];
#pragma unroll
    for (int i = 0; i < 4; ++i)
#pragma unroll
        for (int j = 0; j < 4; ++j)
#pragma unroll
            for (int q = 0; q < 4; ++q) acc[i][j][q] = 0.f;

    uint4 pa0 = Ag0[0], pa1 = Ag1[0], pb0 = Bg0[0], pb1 = Bg1[0];

#pragma unroll 1
    for (int kt = 0; kt < KAUG / 32; ++kt) {
        __syncthreads();
        asm volatile("st.shared.v4.b32 [%0],{%1,%2,%3,%4};" :: "r"(stoA0), "r"(pa0.x), "r"(pa0.y), "r"(pa0.z), "r"(pa0.w));
        asm volatile("st.shared.v4.b32 [%0],{%1,%2,%3,%4};" :: "r"(stoA1), "r"(pa1.x), "r"(pa1.y), "r"(pa1.z), "r"(pa1.w));
        asm volatile("st.shared.v4.b32 [%0],{%1,%2,%3,%4};" :: "r"(stoB0), "r"(pb0.x), "r"(pb0.y), "r"(pb0.z), "r"(pb0.w));
        asm volatile("st.shared.v4.b32 [%0],{%1,%2,%3,%4};" :: "r"(stoB1), "r"(pb1.x), "r"(pb1.y), "r"(pb1.z), "r"(pb1.w));
        __syncthreads();
        if (kt + 1 < KAUG / 32) {
            // 32 bf16 per k-chunk = 64 B; Ag* indexed in uint4 (16 B) units -> +4/iter
            pa0 = Ag0[(kt + 1) * 4]; pa1 = Ag1[(kt + 1) * 4];
            pb0 = Bg0[(kt + 1) * 4]; pb1 = Bg1[(kt + 1) * 4];
        }
#pragma unroll
        for (int ks = 0; ks < 2; ++ks) {
            unsigned af[4][4], bfr[4][2];
#pragma unroll
            for (int mt = 0; mt < 4; ++mt) ldsm_x4(af[mt], aAddr[mt][ks]);
#pragma unroll
            for (int nt = 0; nt < 4; ++nt) ldsm_x2(bfr[nt], bAddr[nt][ks]);
#pragma unroll
            for (int mt = 0; mt < 4; ++mt)
#pragma unroll
                for (int nt = 0; nt < 4; ++nt)
                    mma_bf16(acc[mt][nt], af[mt], bfr[nt]);
        }
    }

    int qr = lane >> 2, qc = (lane & 3) * 2;
#pragma unroll
    for (int mt = 0; mt < 4; ++mt) {
#pragma unroll
        for (int nt = 0; nt < 4; ++nt) {
            int gm = m0 + wm * 64 + mt * 16 + qr;
            int gn = n0 + wn * 32 + nt * 8 + qc;
            float b0 = bi[gn] + bh[gn];
            float b1 = bi[gn + 1] + bh[gn + 1];
            float2 v0 = make_float2(acc[mt][nt][0] + b0, acc[mt][nt][1] + b1);
            float2 v1 = make_float2(acc[mt][nt][2] + b0, acc[mt][nt][3] + b1);
            *(float2*)(g_pre + (size_t)gm * G4 + gn) = v0;
            *(float2*)(g_pre + (size_t)(gm + 8) * G4 + gn) = v1;
        }
    }
}

// ---------------- grid barrier ------------------------------------------------
__device__ __forceinline__ void gridbar(unsigned* cnt, unsigned target) {
    __threadfence();
    __syncthreads();
    if (threadIdx.x == 0) {
        atomicAdd(cnt, 1u);
        while (*(volatile unsigned*)cnt < target) { }
    }
    __syncthreads();
}

// ---------------- persistent recurrent kernel ---------------------------------
// Per step: 128 GEMM items (32 n-tiles x 4 K-slices of 768).
// Item: partial[ksl][64,128-cols] = haug[64,768] * Whaug[128,768]^T
// Block tile 64x128, 8 warps (2x4), warp tile 32x32.
__global__ __launch_bounds__(256) void lstm_layer_bf16(
    const bf16* __restrict__ Wh, int layer, float* __restrict__ out_ext)
{
    float* __restrict__ hptr = layer ? g_h1 : g_h0;
    float* __restrict__ cptr = layer ? g_c1 : g_c0;
    unsigned* bar = &g_bar[layer];

    __shared__ bf16 hs[64 * 40];
    __shared__ bf16 ws[128 * 40];

    int tid = threadIdx.x;
    int lane = tid & 31, wid = tid >> 5;
    int wm = wid >> 2, wn = wid & 3;

    int item = blockIdx.x;                 // < 128 does GEMM
    int n0 = (item & 31) * 128;
    int k0 = (item >> 5) * 768;
    int ksl = item >> 5;

    // global-load mapping: A 1 seg, B 2 segs per thread
    int ra = tid >> 2, sa = tid & 3;       // A rows 0..63
    const bf16* hbase = g_haug + (size_t)ra * KAUG + k0 + sa * 8;
    const uint4* Bg0 = (const uint4*)(Wh + (size_t)(n0 + ra) * KAUG + k0 + sa * 8);
    const uint4* Bg1 = (const uint4*)(Wh + (size_t)(n0 + ra + 64) * KAUG + k0 + sa * 8);

    unsigned sH = (unsigned)__cvta_generic_to_shared(hs);
    unsigned sW = (unsigned)__cvta_generic_to_shared(ws);
    unsigned stoH = sH + ra * 80 + sa * 16;
    unsigned stoW0 = sW + ra * 80 + sa * 16;
    unsigned stoW1 = sW + (ra + 64) * 80 + sa * 16;

    unsigned aAddr[2][2], bAddr[4][2];
#pragma unroll
    for (int mt = 0; mt < 2; ++mt)
#pragma unroll
        for (int ks = 0; ks < 2; ++ks)
            aAddr[mt][ks] = sH + (wm * 32 + mt * 16 + (lane & 15)) * 80 + ks * 32 + ((lane >> 4) & 1) * 16;
#pragma unroll
    for (int nt = 0; nt < 4; ++nt)
#pragma unroll
        for (int ks = 0; ks < 2; ++ks)
            bAddr[nt][ks] = sW + (wn * 32 + nt * 8 + (lane & 7)) * 80 + ks * 32 + ((lane >> 3) & 1) * 16;

    int qr = lane >> 2, qc = (lane & 3) * 2;

    for (int t = 0; t < SS; ++t) {
        // ---- phase 1: split-K step GEMM ----
        if (item < 128) {
            float acc[2][4][4];
#pragma unroll
            for (int i = 0; i < 2; ++i)
#pragma unroll
                for (int j = 0; j < 4; ++j)
#pragma unroll
                    for (int q = 0; q < 4; ++q) acc[i][j][q] = 0.f;

            uint4 pa = __ldcg((const uint4*)hbase);
            uint4 pb0 = Bg0[0], pb1 = Bg1[0];

#pragma unroll 1
            for (int kt = 0; kt < 24; ++kt) {
                __syncthreads();
                asm volatile("st.shared.v4.b32 [%0],{%1,%2,%3,%4};" :: "r"(stoH), "r"(pa.x), "r"(pa.y), "r"(pa.z), "r"(pa.w));
                asm volatile("st.shared.v4.b32 [%0],{%1,%2,%3,%4};" :: "r"(stoW0), "r"(pb0.x), "r"(pb0.y), "r"(pb0.z), "r"(pb0.w));
                asm volatile("st.shared.v4.b32 [%0],{%1,%2,%3,%4};" :: "r"(stoW1), "r"(pb1.x), "r"(pb1.y), "r"(pb1.z), "r"(pb1.w));
                __syncthreads();
                if (kt + 1 < 24) {
                    pa  = __ldcg((const uint4*)(hbase + (kt + 1) * 32));
                    pb0 = Bg0[(kt + 1) * 4];
                    pb1 = Bg1[(kt + 1) * 4];
                }
#pragma unroll
                for (int ks = 0; ks < 2; ++ks) {
                    unsigned af[2][4], bfr[4][2];
#pragma unroll
                    for (int mt = 0; mt < 2; ++mt) ldsm_x4(af[mt], aAddr[mt][ks]);
#pragma unroll
                    for (int nt = 0; nt < 4; ++nt) ldsm_x2(bfr[nt], bAddr[nt][ks]);
#pragma unroll
                    for (int mt = 0; mt < 2; ++mt)
#pragma unroll
                        for (int nt = 0; nt < 4; ++nt)
                            mma_bf16(acc[mt][nt], af[mt], bfr[nt]);
                }
            }

            float* pbase = g_partial + (size_t)ksl * BB * G4;
#pragma unroll
            for (int mt = 0; mt < 2; ++mt) {
#pragma unroll
                for (int nt = 0; nt < 4; ++nt) {
                    int gm = wm * 32 + mt * 16 + qr;
                    int gn = n0 + wn * 32 + nt * 8 + qc;
                    *(float2*)(pbase + (size_t)gm * G4 + gn) =
                        make_float2(acc[mt][nt][0], acc[mt][nt][1]);
                    *(float2*)(pbase + (size_t)(gm + 8) * G4 + gn) =
                        make_float2(acc[mt][nt][2], acc[mt][nt][3]);
                }
            }
        }

        gridbar(bar, (2u * t + 1u) * GRID);

        // ---- phase 2: pointwise gate update ----
        for (int id = blockIdx.x * 256 + tid; id < BB * HH; id += GRID * 256) {
            int b = id >> 10;
            int j = id & (HH - 1);

            const float* pr = g_pre + (size_t)(b * SS + t) * G4 + j;
            float gi = pr[0], gf = pr[HH], gg = pr[2 * HH], go = pr[3 * HH];
#pragma unroll
            for (int s = 0; s < KSL; ++s) {
                const float* pp = g_partial + (size_t)(s * BB + b) * G4 + j;
                gi += __ldcg(pp);
                gf += __ldcg(pp + HH);
                gg += __ldcg(pp + 2 * HH);
                go += __ldcg(pp + 3 * HH);
            }

            float iv = 1.f / (1.f + expf(-gi));
            float fv = 1.f / (1.f + expf(-gf));
            float gv = tanhf(gg);
            float ov = 1.f / (1.f + expf(-go));

            float cn = fv * cptr[id] + iv * gv;
            float hn = ov * tanhf(cn);

            cptr[id] = cn;
            hptr[id] = hn;

            bf16 hi = __float2bfloat16(hn);
            bf16 lo = __float2bfloat16(hn - __bfloat162float(hi));
            bf16* hrow = g_haug + (size_t)b * KAUG;
            hrow[j] = hi; hrow[j + KK] = lo; hrow[j + 2 * KK] = hi;

            if (layer == 0) {
                bf16* xrow = g_xaug + (size_t)(b * SS + t) * KAUG;
                xrow[j] = hi; xrow[j + KK] = lo; xrow[j + 2 * KK] = hi;
            } else {
                out_ext[(size_t)(b * SS + t) * HH + j] = hn;
            }
        }

        gridbar(bar, (2u * t + 2u) * GRID);
    }

    // reset h_aug for the next layer's t=0 (no barrier needed; kernel boundary orders it)
    for (int i = blockIdx.x * 256 + tid; i < BB * KAUG / 2; i += GRID * 256)
        ((unsigned*)g_haug)[i] = 0u;
}

// ---------------- final h_n / c_n stacks --------------------------------------
__global__ void finalize_kernel(float* __restrict__ out_h, float* __restrict__ out_c)
{
    int i = blockIdx.x * 256 + threadIdx.x;
    out_h[i]           = g_h0[i];
    out_h[BB * HH + i] = g_h1[i];
    out_c[i]           = g_c0[i];
    out_c[BB * HH + i] = g_c1[i];
}

// ---------------- launch --------------------------------------------------------
extern "C" void kernel_launch(void* const* d_in, const int* in_sizes, int n_in,
                              void* d_out, int out_size)
{
    const float* x   = (const float*)d_in[0];
    const float* Wi0 = (const float*)d_in[1];
    const float* Wh0 = (const float*)d_in[2];
    const float* bi0 = (const float*)d_in[3];
    const float* bh0 = (const float*)d_in[4];
    const float* Wi1 = (const float*)d_in[5];
    const float* Wh1 = (const float*)d_in[6];
    const float* bi1 = (const float*)d_in[7];
    const float* bh1 = (const float*)d_in[8];

    float* out   = (float*)d_out;
    float* out_h = out + (size_t)BB * SS * HH;
    float* out_c = out_h + (size_t)2 * BB * HH;

    bf16 *wi0a, *wh0a, *wi1a, *wh1a, *xaug;
    cudaGetSymbolAddress((void**)&wi0a, g_wi0aug);
    cudaGetSymbolAddress((void**)&wh0a, g_wh0aug);
    cudaGetSymbolAddress((void**)&wi1a, g_wi1aug);
    cudaGetSymbolAddress((void**)&wh1a, g_wh1aug);
    cudaGetSymbolAddress((void**)&xaug, g_xaug);

    init_state_kernel<<<384, 256>>>();

    convert_w_kernel<<<G4 * KK / 256, 256>>>(Wi0, wi0a);
    convert_w_kernel<<<G4 * KK / 256, 256>>>(Wh0, wh0a);
    convert_w_kernel<<<G4 * KK / 256, 256>>>(Wi1, wi1a);
    convert_w_kernel<<<G4 * KK / 256, 256>>>(Wh1, wh1a);
    convert_x_kernel<<<MTOT * KK / 256, 256>>>(x);

    dim3 gGrid(G4 / 128, MTOT / 128);   // (32, 256)

    gemm_bias_bf16<<<gGrid, 256>>>(xaug, wi0a, bi0, bh0);
    lstm_layer_bf16<<<GRID, 256>>>(wh0a, 0, out);

    gemm_bias_bf16<<<gGrid, 256>>>(xaug, wi1a, bi1, bh1);
    lstm_layer_bf16<<<GRID, 256>>>(wh1a, 1, out);

    finalize_kernel<<<BB * HH / 256, 256>>>(out_h, out_c);
}

// round 17
// speedup vs baseline: 1.3713x; 1.0111x over previous
#include <cuda_runtime.h>
#include <cuda_bf16.h>
#include <math.h>

#define BB 64
#define SS 512
#define HH 1024
#define G4 4096
#define KK 1024
#define KAUG 3072
#define KSL 4          // K-slices in recurrent split-K (768 each)
#define GRID 148
#define MTOT (BB * SS) // 32768

typedef __nv_bfloat16 bf16;

// ---------------- scratch (static device globals; no runtime allocation) ----
__device__ float g_pre[(size_t)MTOT * G4];              // 512 MB fp32
__device__ bf16  g_xaug[(size_t)MTOT * KAUG];           // 201 MB: layer input, aug [hi|lo|hi]
__device__ bf16  g_wi0aug[(size_t)G4 * KAUG];           // 25 MB each
__device__ bf16  g_wh0aug[(size_t)G4 * KAUG];
__device__ bf16  g_wi1aug[(size_t)G4 * KAUG];
__device__ bf16  g_wh1aug[(size_t)G4 * KAUG];
__device__ bf16  g_haug[BB * KAUG];                     // current h, aug
__device__ float g_partial[(size_t)KSL * BB * G4];      // 4 MB split-K partials
__device__ float g_h0[BB * HH];
__device__ float g_c0[BB * HH];
__device__ float g_h1[BB * HH];
__device__ float g_c1[BB * HH];
__device__ unsigned g_bar[2];

// ---------------- PTX helpers -----------------------------------------------
__device__ __forceinline__ void mma_bf16(float* c, const unsigned* a, const unsigned* b) {
    asm volatile(
        "mma.sync.aligned.m16n8k16.row.col.f32.bf16.bf16.f32 "
        "{%0,%1,%2,%3},{%4,%5,%6,%7},{%8,%9},{%0,%1,%2,%3};"
        : "+f"(c[0]), "+f"(c[1]), "+f"(c[2]), "+f"(c[3])
        : "r"(a[0]), "r"(a[1]), "r"(a[2]), "r"(a[3]), "r"(b[0]), "r"(b[1]));
}
__device__ __forceinline__ void ldsm_x4(unsigned* r, unsigned addr) {
    asm volatile("ldmatrix.sync.aligned.m8n8.x4.shared.b16 {%0,%1,%2,%3},[%4];"
                 : "=r"(r[0]), "=r"(r[1]), "=r"(r[2]), "=r"(r[3]) : "r"(addr));
}
__device__ __forceinline__ void ldsm_x2(unsigned* r, unsigned addr) {
    asm volatile("ldmatrix.sync.aligned.m8n8.x2.shared.b16 {%0,%1},[%2];"
                 : "=r"(r[0]), "=r"(r[1]) : "r"(addr));
}

// ---------------- init --------------------------------------------------------
__global__ void init_state_kernel() {
    int i = blockIdx.x * 256 + threadIdx.x;          // grid 384*256 = 98304
    if (i < BB * HH) { g_h0[i] = 0.f; g_c0[i] = 0.f; g_h1[i] = 0.f; g_c1[i] = 0.f; }
    if (i < 2) g_bar[i] = 0u;
    if (i < BB * KAUG / 2) ((unsigned*)g_haug)[i] = 0u;
}

// ---------------- fp32 -> bf16 split conversions ------------------------------
// weights: aug layout [wh | wh | wl]
__global__ void convert_w_kernel(const float* __restrict__ W, bf16* __restrict__ Waug) {
    int idx = blockIdx.x * 256 + threadIdx.x;        // over 4096*1024
    int g = idx >> 10, k = idx & (KK - 1);
    float v = W[idx];
    bf16 hi = __float2bfloat16(v);
    bf16 lo = __float2bfloat16(v - __bfloat162float(hi));
    bf16* row = Waug + (size_t)g * KAUG;
    row[k] = hi; row[k + KK] = hi; row[k + 2 * KK] = lo;
}
// activations: aug layout [hi | lo | hi]
__global__ void convert_x_kernel(const float* __restrict__ X) {
    int idx = blockIdx.x * 256 + threadIdx.x;        // over 32768*1024
    int m = idx >> 10, k = idx & (KK - 1);
    float v = X[idx];
    bf16 hi = __float2bfloat16(v);
    bf16 lo = __float2bfloat16(v - __bfloat162float(hi));
    bf16* row = g_xaug + (size_t)m * KAUG;
    row[k] = hi; row[k + KK] = lo; row[k + 2 * KK] = hi;
}

// ---------------- input-projection GEMM (bf16 tensor-core) --------------------
// g_pre[M,4096] = Aaug[M,3072] * Waug[4096,3072]^T + bi + bh
// Block 128x128, k-chunk 32, 8 warps (2x4), warp tile 64x32.
__global__ __launch_bounds__(256) void gemm_bias_bf16(
    const bf16* __restrict__ A, const bf16* __restrict__ W,
    const float* __restrict__ bi, const float* __restrict__ bh)
{
    __shared__ bf16 As[128 * 40];
    __shared__ bf16 Bs[128 * 40];

    int tid = threadIdx.x;
    int lane = tid & 31, wid = tid >> 5;
    int wm = wid >> 2, wn = wid & 3;
    int m0 = blockIdx.y * 128, n0 = blockIdx.x * 128;

    // global-load mapping: 2 x 16B segs for A, 2 for B per thread
    int r0 = tid >> 2, s0 = tid & 3;
    int r1 = r0 + 64;
    const uint4* Ag0 = (const uint4*)(A + (size_t)(m0 + r0) * KAUG + s0 * 8);
    const uint4* Ag1 = (const uint4*)(A + (size_t)(m0 + r1) * KAUG + s0 * 8);
    const uint4* Bg0 = (const uint4*)(W + (size_t)(n0 + r0) * KAUG + s0 * 8);
    const uint4* Bg1 = (const uint4*)(W + (size_t)(n0 + r1) * KAUG + s0 * 8);

    unsigned sA = (unsigned)__cvta_generic_to_shared(As);
    unsigned sB = (unsigned)__cvta_generic_to_shared(Bs);
    unsigned stoA0 = sA + r0 * 80 + s0 * 16;
    unsigned stoA1 = sA + r1 * 80 + s0 * 16;
    unsigned stoB0 = sB + r0 * 80 + s0 * 16;
    unsigned stoB1 = sB + r1 * 80 + s0 * 16;

    // ldmatrix lane addresses (constant over k-iters)
    unsigned aAddr[4][2], bAddr[4][2];
#pragma unroll
    for (int mt = 0; mt < 4; ++mt)
#pragma unroll
        for (int ks = 0; ks < 2; ++ks)
            aAddr[mt][ks] = sA + (wm * 64 + mt * 16 + (lane & 15)) * 80 + ks * 32 + ((lane >> 4) & 1) * 16;
#pragma unroll
    for (int nt = 0; nt < 4; ++nt)
#pragma unroll
        for (int ks = 0; ks < 2; ++ks)
            bAddr[nt][ks] = sB + (wn * 32 + nt * 8 + (lane & 7)) * 80 + ks * 32 + ((lane >> 3) & 1) * 16;

    float acc[4][4][4];
#pragma unroll
    for (int i = 0; i < 4; ++i)
#pragma unroll
        for (int j = 0; j < 4; ++j)
#pragma unroll
            for (int q = 0; q < 4; ++q) acc[i][j][q] = 0.f;

    uint4 pa0 = Ag0[0], pa1 = Ag1[0], pb0 = Bg0[0], pb1 = Bg1[0];

#pragma unroll 1
    for (int kt = 0; kt < KAUG / 32; ++kt) {
        __syncthreads();
        asm volatile("st.shared.v4.b32 [%0],{%1,%2,%3,%4};" :: "r"(stoA0), "r"(pa0.x), "r"(pa0.y), "r"(pa0.z), "r"(pa0.w));
        asm volatile("st.shared.v4.b32 [%0],{%1,%2,%3,%4};" :: "r"(stoA1), "r"(pa1.x), "r"(pa1.y), "r"(pa1.z), "r"(pa1.w));
        asm volatile("st.shared.v4.b32 [%0],{%1,%2,%3,%4};" :: "r"(stoB0), "r"(pb0.x), "r"(pb0.y), "r"(pb0.z), "r"(pb0.w));
        asm volatile("st.shared.v4.b32 [%0],{%1,%2,%3,%4};" :: "r"(stoB1), "r"(pb1.x), "r"(pb1.y), "r"(pb1.z), "r"(pb1.w));
        __syncthreads();
        if (kt + 1 < KAUG / 32) {
            // 32 bf16 per k-chunk = 64 B; Ag* indexed in uint4 (16 B) units -> +4/iter
            pa0 = Ag0[(kt + 1) * 4]; pa1 = Ag1[(kt + 1) * 4];
            pb0 = Bg0[(kt + 1) * 4]; pb1 = Bg1[(kt + 1) * 4];
        }
#pragma unroll
        for (int ks = 0; ks < 2; ++ks) {
            unsigned af[4][4], bfr[4][2];
#pragma unroll
            for (int mt = 0; mt < 4; ++mt) ldsm_x4(af[mt], aAddr[mt][ks]);
#pragma unroll
            for (int nt = 0; nt < 4; ++nt) ldsm_x2(bfr[nt], bAddr[nt][ks]);
#pragma unroll
            for (int mt = 0; mt < 4; ++mt)
#pragma unroll
                for (int nt = 0; nt < 4; ++nt)
                    mma_bf16(acc[mt][nt], af[mt], bfr[nt]);
        }
    }

    int qr = lane >> 2, qc = (lane & 3) * 2;
#pragma unroll
    for (int mt = 0; mt < 4; ++mt) {
#pragma unroll
        for (int nt = 0; nt < 4; ++nt) {
            int gm = m0 + wm * 64 + mt * 16 + qr;
            int gn = n0 + wn * 32 + nt * 8 + qc;
            float b0 = bi[gn] + bh[gn];
            float b1 = bi[gn + 1] + bh[gn + 1];
            float2 v0 = make_float2(acc[mt][nt][0] + b0, acc[mt][nt][1] + b1);
            float2 v1 = make_float2(acc[mt][nt][2] + b0, acc[mt][nt][3] + b1);
            *(float2*)(g_pre + (size_t)gm * G4 + gn) = v0;
            *(float2*)(g_pre + (size_t)(gm + 8) * G4 + gn) = v1;
        }
    }
}

// ---------------- grid barrier ------------------------------------------------
__device__ __forceinline__ void gridbar(unsigned* cnt, unsigned target) {
    __threadfence();
    __syncthreads();
    if (threadIdx.x == 0) {
        atomicAdd(cnt, 1u);
        while (*(volatile unsigned*)cnt < target) { }
    }
    __syncthreads();
}

// ---------------- persistent recurrent kernel ---------------------------------
// Per step: 128 GEMM items (32 n-tiles x 4 K-slices of 768).
// Item: partial[ksl][64,128-cols] = haug[64,768] * Whaug[128,768]^T
// Block tile 64x128, 8 warps (2x4), warp tile 32x32.
__global__ __launch_bounds__(256) void lstm_layer_bf16(
    const bf16* __restrict__ Wh, int layer, float* __restrict__ out_ext)
{
    float* __restrict__ hptr = layer ? g_h1 : g_h0;
    float* __restrict__ cptr = layer ? g_c1 : g_c0;
    unsigned* bar = &g_bar[layer];

    __shared__ bf16 hs[64 * 40];
    __shared__ bf16 ws[128 * 40];

    int tid = threadIdx.x;
    int lane = tid & 31, wid = tid >> 5;
    int wm = wid >> 2, wn = wid & 3;

    int item = blockIdx.x;                 // < 128 does GEMM
    int n0 = (item & 31) * 128;
    int k0 = (item >> 5) * 768;
    int ksl = item >> 5;

    // global-load mapping: A 1 seg, B 2 segs per thread
    int ra = tid >> 2, sa = tid & 3;       // A rows 0..63
    const bf16* hbase = g_haug + (size_t)ra * KAUG + k0 + sa * 8;
    const uint4* Bg0 = (const uint4*)(Wh + (size_t)(n0 + ra) * KAUG + k0 + sa * 8);
    const uint4* Bg1 = (const uint4*)(Wh + (size_t)(n0 + ra + 64) * KAUG + k0 + sa * 8);

    unsigned sH = (unsigned)__cvta_generic_to_shared(hs);
    unsigned sW = (unsigned)__cvta_generic_to_shared(ws);
    unsigned stoH = sH + ra * 80 + sa * 16;
    unsigned stoW0 = sW + ra * 80 + sa * 16;
    unsigned stoW1 = sW + (ra + 64) * 80 + sa * 16;

    unsigned aAddr[2][2], bAddr[4][2];
#pragma unroll
    for (int mt = 0; mt < 2; ++mt)
#pragma unroll
        for (int ks = 0; ks < 2; ++ks)
            aAddr[mt][ks] = sH + (wm * 32 + mt * 16 + (lane & 15)) * 80 + ks * 32 + ((lane >> 4) & 1) * 16;
#pragma unroll
    for (int nt = 0; nt < 4; ++nt)
#pragma unroll
        for (int ks = 0; ks < 2; ++ks)
            bAddr[nt][ks] = sW + (wn * 32 + nt * 8 + (lane & 7)) * 80 + ks * 32 + ((lane >> 3) & 1) * 16;

    int qr = lane >> 2, qc = (lane & 3) * 2;

    for (int t = 0; t < SS; ++t) {
        // ---- phase 1: split-K step GEMM ----
        if (item < 128) {
            float acc[2][4][4];
#pragma unroll
            for (int i = 0; i < 2; ++i)
#pragma unroll
                for (int j = 0; j < 4; ++j)
#pragma unroll
                    for (int q = 0; q < 4; ++q) acc[i][j][q] = 0.f;

            uint4 pa = __ldcg((const uint4*)hbase);
            uint4 pb0 = Bg0[0], pb1 = Bg1[0];

#pragma unroll 1
            for (int kt = 0; kt < 24; ++kt) {
                __syncthreads();
                asm volatile("st.shared.v4.b32 [%0],{%1,%2,%3,%4};" :: "r"(stoH), "r"(pa.x), "r"(pa.y), "r"(pa.z), "r"(pa.w));
                asm volatile("st.shared.v4.b32 [%0],{%1,%2,%3,%4};" :: "r"(stoW0), "r"(pb0.x), "r"(pb0.y), "r"(pb0.z), "r"(pb0.w));
                asm volatile("st.shared.v4.b32 [%0],{%1,%2,%3,%4};" :: "r"(stoW1), "r"(pb1.x), "r"(pb1.y), "r"(pb1.z), "r"(pb1.w));
                __syncthreads();
                if (kt + 1 < 24) {
                    pa  = __ldcg((const uint4*)(hbase + (kt + 1) * 32));
                    pb0 = Bg0[(kt + 1) * 4];
                    pb1 = Bg1[(kt + 1) * 4];
                }
#pragma unroll
                for (int ks = 0; ks < 2; ++ks) {
                    unsigned af[2][4], bfr[4][2];
#pragma unroll
                    for (int mt = 0; mt < 2; ++mt) ldsm_x4(af[mt], aAddr[mt][ks]);
#pragma unroll
                    for (int nt = 0; nt < 4; ++nt) ldsm_x2(bfr[nt], bAddr[nt][ks]);
#pragma unroll
                    for (int mt = 0; mt < 2; ++mt)
#pragma unroll
                        for (int nt = 0; nt < 4; ++nt)
                            mma_bf16(acc[mt][nt], af[mt], bfr[nt]);
                }
            }

            float* pbase = g_partial + (size_t)ksl * BB * G4;
#pragma unroll
            for (int mt = 0; mt < 2; ++mt) {
#pragma unroll
                for (int nt = 0; nt < 4; ++nt) {
                    int gm = wm * 32 + mt * 16 + qr;
                    int gn = n0 + wn * 32 + nt * 8 + qc;
                    *(float2*)(pbase + (size_t)gm * G4 + gn) =
                        make_float2(acc[mt][nt][0], acc[mt][nt][1]);
                    *(float2*)(pbase + (size_t)(gm + 8) * G4 + gn) =
                        make_float2(acc[mt][nt][2], acc[mt][nt][3]);
                }
            }
        }

        gridbar(bar, (2u * t + 1u) * GRID);

        // ---- phase 2: pointwise gate update ----
        for (int id = blockIdx.x * 256 + tid; id < BB * HH; id += GRID * 256) {
            int b = id >> 10;
            int j = id & (HH - 1);

            const float* pr = g_pre + (size_t)(b * SS + t) * G4 + j;
            float gi = pr[0], gf = pr[HH], gg = pr[2 * HH], go = pr[3 * HH];
#pragma unroll
            for (int s = 0; s < KSL; ++s) {
                const float* pp = g_partial + (size_t)(s * BB + b) * G4 + j;
                gi += __ldcg(pp);
                gf += __ldcg(pp + HH);
                gg += __ldcg(pp + 2 * HH);
                go += __ldcg(pp + 3 * HH);
            }

            float iv = 1.f / (1.f + expf(-gi));
            float fv = 1.f / (1.f + expf(-gf));
            float gv = tanhf(gg);
            float ov = 1.f / (1.f + expf(-go));

            float cn = fv * cptr[id] + iv * gv;
            float hn = ov * tanhf(cn);

            cptr[id] = cn;
            hptr[id] = hn;

            bf16 hi = __float2bfloat16(hn);
            bf16 lo = __float2bfloat16(hn - __bfloat162float(hi));
            bf16* hrow = g_haug + (size_t)b * KAUG;
            hrow[j] = hi; hrow[j + KK] = lo; hrow[j + 2 * KK] = hi;

            if (layer == 0) {
                bf16* xrow = g_xaug + (size_t)(b * SS + t) * KAUG;
                xrow[j] = hi; xrow[j + KK] = lo; xrow[j + 2 * KK] = hi;
            } else {
                out_ext[(size_t)(b * SS + t) * HH + j] = hn;
            }
        }

        gridbar(bar, (2u * t + 2u) * GRID);
    }

    // reset h_aug for the next layer's t=0 (no barrier needed; kernel boundary orders it)
    for (int i = blockIdx.x * 256 + tid; i < BB * KAUG / 2; i += GRID * 256)
        ((unsigned*)g_haug)[i] = 0u;
}

// ---------------- final h_n / c_n stacks --------------------------------------
__global__ void finalize_kernel(float* __restrict__ out_h, float* __restrict__ out_c)
{
    int i = blockIdx.x * 256 + threadIdx.x;
    out_h[i]           = g_h0[i];
    out_h[BB * HH + i] = g_h1[i];
    out_c[i]           = g_c0[i];
    out_c[BB * HH + i] = g_c1[i];
}

// ---------------- launch --------------------------------------------------------
extern "C" void kernel_launch(void* const* d_in, const int* in_sizes, int n_in,
                              void* d_out, int out_size)
{
    const float* x   = (const float*)d_in[0];
    const float* Wi0 = (const float*)d_in[1];
    const float* Wh0 = (const float*)d_in[2];
    const float* bi0 = (const float*)d_in[3];
    const float* bh0 = (const float*)d_in[4];
    const float* Wi1 = (const float*)d_in[5];
    const float* Wh1 = (const float*)d_in[6];
    const float* bi1 = (const float*)d_in[7];
    const float* bh1 = (const float*)d_in[8];

    float* out   = (float*)d_out;
    float* out_h = out + (size_t)BB * SS * HH;
    float* out_c = out_h + (size_t)2 * BB * HH;

    bf16 *wi0a, *wh0a, *wi1a, *wh1a, *xaug;
    cudaGetSymbolAddress((void**)&wi0a, g_wi0aug);
    cudaGetSymbolAddress((void**)&wh0a, g_wh0aug);
    cudaGetSymbolAddress((void**)&wi1a, g_wi1aug);
    cudaGetSymbolAddress((void**)&wh1a, g_wh1aug);
    cudaGetSymbolAddress((void**)&xaug, g_xaug);

    init_state_kernel<<<384, 256>>>();

    convert_w_kernel<<<G4 * KK / 256, 256>>>(Wi0, wi0a);
    convert_w_kernel<<<G4 * KK / 256, 256>>>(Wh0, wh0a);
    convert_w_kernel<<<G4 * KK / 256, 256>>>(Wi1, wi1a);
    convert_w_kernel<<<G4 * KK / 256, 256>>>(Wh1, wh1a);
    convert_x_kernel<<<MTOT * KK / 256, 256>>>(x);

    dim3 gGrid(G4 / 128, MTOT / 128);   // (32, 256)

    gemm_bias_bf16<<<gGrid, 256>>>(xaug, wi0a, bi0, bh0);
    lstm_layer_bf16<<<GRID, 256>>>(wh0a, 0, out);

    gemm_bias_bf16<<<gGrid, 256>>>(xaug, wi1a, bi1, bh1);
    lstm_layer_bf16<<<GRID, 256>>>(wh1a, 1, out);

    finalize_kernel<<<BB * HH / 256, 256>>>(out_h, out_c);
}